// round 2
// baseline (speedup 1.0000x reference)
#include <cuda_runtime.h>

#define BDIM   256
#define TILE_M 64
#define NCH    512
#define HID    64
#define XS     516   // x / tanh smem row stride (mod 32 == 4 -> conflict-free multi-row reads)
#define HS     68    // h1 smem row stride
#define WS2    132   // w2 stage row stride

// Pre-transposed weights (written by prep_kernel each launch; deterministic).
__device__ __align__(16) float g_w1t[513 * 64];   // w1t[k][h] = W1[h][k], k=0..512 (512 = epsilon column)
__device__ __align__(16) float g_w2t[64 * 512];   // w2t[h][n] = W2[n][h]

__global__ void prep_kernel(const float* __restrict__ W1, const float* __restrict__ W2) {
    int idx = blockIdx.x * blockDim.x + threadIdx.x;
    if (idx < 513 * 64) {
        int k = idx >> 6, h = idx & 63;
        g_w1t[idx] = W1[h * 513 + k];
    }
    if (idx < 64 * 512) {
        int h = idx >> 9, n = idx & 511;
        g_w2t[idx] = W2[n * 64 + h];
    }
}

__device__ __forceinline__ float fast_tanh(float x) {
    float ax = fabsf(x);
    float e  = __expf(-2.0f * ax);                 // MUFU.EX2 path, ~2 ulp
    float t  = __fdividef(1.0f - e, 1.0f + e);     // MUFU.RCP path, ~2 ulp
    return copysignf(t, x);
}

__global__ __launch_bounds__(BDIM, 1)
void fused_kernel(const float* __restrict__ x_cpm,
                  const float* __restrict__ x_cons,
                  const float* __restrict__ cap,
                  const float* __restrict__ b1,
                  const float* __restrict__ b2,
                  float* __restrict__ out) {
    extern __shared__ float sm[];
    float* s_x      = sm;                          // TILE_M * XS = 33024  (x tile, later tanh buffer)
    float* s_w      = s_x + TILE_M * XS;           // 8448 (weight stage, shared by both GEMMs)
    float* s_h1     = s_w + 8448;                  // TILE_M * HS = 4352
    float* s_cap    = s_h1 + TILE_M * HS;          // 512
    float* s_icap   = s_cap + 512;                 // 512
    float* s_eps    = s_icap + 512;                // 64
    float* s_scale  = s_eps + 64;                  // 64
    float* s_rowsum = s_scale + 64;                // 64
    float* s_red    = s_rowsum + 64;               // 9

    const int tid  = threadIdx.x;
    const int row0 = blockIdx.x * TILE_M;
    const int cg   = tid & 15;   // 16 col-groups
    const int rg   = tid >> 4;   // 16 row-groups (4 rows each)

    // ---------- Phase 0: cap, 1/cap, cap_sum partials, x tile ----------
    float capp = 0.f;
    for (int k = tid; k < NCH; k += BDIM) {
        float v = cap[k];
        s_cap[k]  = v;
        s_icap[k] = 1.0f / v;
        capp += v;
    }
    #pragma unroll
    for (int off = 16; off; off >>= 1)
        capp += __shfl_down_sync(0xffffffffu, capp, off);
    if ((tid & 31) == 0) s_red[tid >> 5] = capp;

    const float4* xg = (const float4*)(x_cpm + (size_t)row0 * NCH);
    for (int idx = tid; idx < TILE_M * (NCH / 4); idx += BDIM) {
        int r = idx >> 7, c4 = idx & 127;
        *(float4*)(s_x + r * XS + c4 * 4) = xg[r * (NCH / 4) + c4];
    }
    __syncthreads();

    if (tid == 0) {
        float cs = 0.f;
        #pragma unroll
        for (int i = 0; i < 8; i++) cs += s_red[i];
        s_red[8] = cs;
    }

    // ---------- Phase 1: raw dot(x_row, cap), 4 threads per row ----------
    {
        int r = tid >> 2, s = tid & 3;
        const float* xr = s_x + r * XS;
        float p = 0.f;
        #pragma unroll 8
        for (int i = 0; i < NCH / 4; i++) {
            int k = s + 4 * i;
            p = fmaf(xr[k], s_cap[k], p);
        }
        p += __shfl_down_sync(0xffffffffu, p, 2, 4);
        p += __shfl_down_sync(0xffffffffu, p, 1, 4);
        if (s == 0) s_eps[r] = p;
    }
    __syncthreads();
    const float cap_sum = s_red[8];
    if (tid < TILE_M) {
        // epsilon = x_cons - dot / cap_sum
        s_eps[tid] = x_cons[row0 + tid] - s_eps[tid] / cap_sum;
    }
    // (visible to all before GEMM1 epilogue via the chunk-loop barriers)

    // ---------- Phase 2: GEMM1  h1[64r][64h] = relu(x @ W1a^T + eps*w1e + b1) ----------
    float acc[4][4];
    #pragma unroll
    for (int i = 0; i < 4; i++)
        #pragma unroll
        for (int j = 0; j < 4; j++) acc[i][j] = 0.f;

    for (int kc = 0; kc < NCH; kc += 128) {
        __syncthreads();
        const float4* wsrc = (const float4*)(g_w1t + kc * 64);
        for (int i = tid; i < 128 * 16; i += BDIM)
            ((float4*)s_w)[i] = wsrc[i];
        __syncthreads();

        const float* xr0 = s_x + (4 * rg) * XS + kc;
        #pragma unroll 16
        for (int kk = 0; kk < 128; kk++) {
            float4 w = *(const float4*)(s_w + kk * 64 + 4 * cg);
            #pragma unroll
            for (int i = 0; i < 4; i++) {
                float xv = xr0[i * XS + kk];
                acc[i][0] = fmaf(xv, w.x, acc[i][0]);
                acc[i][1] = fmaf(xv, w.y, acc[i][1]);
                acc[i][2] = fmaf(xv, w.z, acc[i][2]);
                acc[i][3] = fmaf(xv, w.w, acc[i][3]);
            }
        }
    }
    {
        float4 we = *(const float4*)(g_w1t + 512 * 64 + 4 * cg);  // epsilon column weights
        float4 bb = *(const float4*)(b1 + 4 * cg);
        #pragma unroll
        for (int i = 0; i < 4; i++) {
            float ev = s_eps[4 * rg + i];
            float4 h;
            h.x = fmaxf(acc[i][0] + ev * we.x + bb.x, 0.f);
            h.y = fmaxf(acc[i][1] + ev * we.y + bb.y, 0.f);
            h.z = fmaxf(acc[i][2] + ev * we.z + bb.z, 0.f);
            h.w = fmaxf(acc[i][3] + ev * we.w + bb.w, 0.f);
            *(float4*)(s_h1 + (4 * rg + i) * HS + 4 * cg) = h;
        }
    }

    // ---------- Phase 3: GEMM2 + tanh + row sums (tanh overwrites s_x) ----------
    float rsum[4] = {0.f, 0.f, 0.f, 0.f};
    for (int nc = 0; nc < NCH; nc += 128) {
        __syncthreads();
        for (int i = tid; i < 64 * 32; i += BDIM) {
            int kk = i >> 5, c4 = i & 31;
            *(float4*)(s_w + kk * WS2 + c4 * 4) =
                *(const float4*)(g_w2t + kk * 512 + nc + c4 * 4);
        }
        __syncthreads();

        float a2[4][8];
        #pragma unroll
        for (int i = 0; i < 4; i++)
            #pragma unroll
            for (int j = 0; j < 8; j++) a2[i][j] = 0.f;

        const float* hb = s_h1 + (4 * rg) * HS;
        #pragma unroll 8
        for (int kk = 0; kk < HID; kk++) {
            float4 wa = *(const float4*)(s_w + kk * WS2 + 8 * cg);
            float4 wb = *(const float4*)(s_w + kk * WS2 + 8 * cg + 4);
            #pragma unroll
            for (int i = 0; i < 4; i++) {
                float hv = hb[i * HS + kk];
                a2[i][0] = fmaf(hv, wa.x, a2[i][0]);
                a2[i][1] = fmaf(hv, wa.y, a2[i][1]);
                a2[i][2] = fmaf(hv, wa.z, a2[i][2]);
                a2[i][3] = fmaf(hv, wa.w, a2[i][3]);
                a2[i][4] = fmaf(hv, wb.x, a2[i][4]);
                a2[i][5] = fmaf(hv, wb.y, a2[i][5]);
                a2[i][6] = fmaf(hv, wb.z, a2[i][6]);
                a2[i][7] = fmaf(hv, wb.w, a2[i][7]);
            }
        }

        float4 b2a = *(const float4*)(b2 + nc + 8 * cg);
        float4 b2b = *(const float4*)(b2 + nc + 8 * cg + 4);
        #pragma unroll
        for (int i = 0; i < 4; i++) {
            float t0 = fast_tanh(a2[i][0] + b2a.x);
            float t1 = fast_tanh(a2[i][1] + b2a.y);
            float t2 = fast_tanh(a2[i][2] + b2a.z);
            float t3 = fast_tanh(a2[i][3] + b2a.w);
            float t4 = fast_tanh(a2[i][4] + b2b.x);
            float t5 = fast_tanh(a2[i][5] + b2b.y);
            float t6 = fast_tanh(a2[i][6] + b2b.z);
            float t7 = fast_tanh(a2[i][7] + b2b.w);
            rsum[i] += ((t0 + t1) + (t2 + t3)) + ((t4 + t5) + (t6 + t7));
            float* dst = s_x + (4 * rg + i) * XS + nc + 8 * cg;
            *(float4*)(dst)     = make_float4(t0, t1, t2, t3);
            *(float4*)(dst + 4) = make_float4(t4, t5, t6, t7);
        }
    }

    // reduce row sums across the 16 col-groups (lanes cg 0..15 per half-warp)
    #pragma unroll
    for (int i = 0; i < 4; i++) {
        float v = rsum[i];
        v += __shfl_down_sync(0xffffffffu, v, 8, 16);
        v += __shfl_down_sync(0xffffffffu, v, 4, 16);
        v += __shfl_down_sync(0xffffffffu, v, 2, 16);
        v += __shfl_down_sync(0xffffffffu, v, 1, 16);
        if (cg == 0) s_rowsum[4 * rg + i] = v;
    }
    __syncthreads();
    if (tid < TILE_M)
        s_scale[tid] = s_eps[tid] * cap_sum / s_rowsum[tid];
    __syncthreads();

    // ---------- Phase 4: out = x + tanh * scale / cap  (x re-read from GMEM) ----------
    float4* og = (float4*)(out + (size_t)row0 * NCH);
    for (int idx = tid; idx < TILE_M * (NCH / 4); idx += BDIM) {
        int r = idx >> 7, c4 = idx & 127;
        float4 xv = xg[r * (NCH / 4) + c4];
        float4 tv = *(const float4*)(s_x + r * XS + c4 * 4);
        float4 ic = *(const float4*)(s_icap + c4 * 4);
        float  sc = s_scale[r];
        float4 o;
        o.x = fmaf(tv.x * sc, ic.x, xv.x);
        o.y = fmaf(tv.y * sc, ic.y, xv.y);
        o.z = fmaf(tv.z * sc, ic.z, xv.z);
        o.w = fmaf(tv.w * sc, ic.w, xv.w);
        og[r * (NCH / 4) + c4] = o;
    }
}

static constexpr size_t SMEM_BYTES =
    (size_t)(TILE_M * XS + 8448 + TILE_M * HS + 512 + 512 + 64 + 64 + 64 + 9) * sizeof(float);

extern "C" void kernel_launch(void* const* d_in, const int* in_sizes, int n_in,
                              void* d_out, int out_size) {
    const float* x_cpm  = (const float*)d_in[0];
    const float* x_cons = (const float*)d_in[1];
    const float* cap    = (const float*)d_in[2];
    const float* W1     = (const float*)d_in[3];
    const float* b1     = (const float*)d_in[4];
    const float* W2     = (const float*)d_in[5];
    const float* b2     = (const float*)d_in[6];
    float* out = (float*)d_out;

    cudaFuncSetAttribute(fused_kernel, cudaFuncAttributeMaxDynamicSharedMemorySize,
                         (int)SMEM_BYTES);

    prep_kernel<<<129, 256>>>(W1, W2);

    const int B = 65536;
    fused_kernel<<<B / TILE_M, BDIM, SMEM_BYTES>>>(x_cpm, x_cons, cap, b1, b2, out);
}

// round 4
// speedup vs baseline: 1.1090x; 1.1090x over previous
#include <cuda_runtime.h>

#define BDIM   512
#define TILE_M 64
#define NCH    512
#define HID    64
#define XS     516   // x / tanh smem row stride (floats); 516 % 4 == 0 (float4), 2*516 % 32 == 8 (bank-skew)
#define HS     68    // h1 smem row stride
#define WS2    132   // w2 stage row stride

// Pre-transposed weights (written by prep_kernel each launch; deterministic).
__device__ __align__(16) float g_w1t[513 * 64];   // w1t[k][h] = W1[h][k], k=512 = epsilon column
__device__ __align__(16) float g_w2t[64 * 512];   // w2t[h][n] = W2[n][h]

__global__ void prep_kernel(const float* __restrict__ W1, const float* __restrict__ W2) {
    int idx = blockIdx.x * blockDim.x + threadIdx.x;
    if (idx < 513 * 64) {
        int k = idx >> 6, h = idx & 63;
        g_w1t[idx] = W1[h * 513 + k];
    }
    if (idx < 64 * 512) {
        int h = idx >> 9, n = idx & 511;
        g_w2t[idx] = W2[n * 64 + h];
    }
}

__device__ __forceinline__ float fast_tanh(float x) {
    float ax = fabsf(x);
    float e  = __expf(-2.0f * ax);
    float t  = __fdividef(1.0f - e, 1.0f + e);
    return copysignf(t, x);
}

// acc[0..3] += a * wv.{x,y,z,w}
__device__ __forceinline__ void fma4(float* acc, float a, float4 wv) {
    acc[0] = fmaf(a, wv.x, acc[0]);
    acc[1] = fmaf(a, wv.y, acc[1]);
    acc[2] = fmaf(a, wv.z, acc[2]);
    acc[3] = fmaf(a, wv.w, acc[3]);
}

__global__ __launch_bounds__(BDIM, 1)
void fused_kernel(const float* __restrict__ x_cpm,
                  const float* __restrict__ x_cons,
                  const float* __restrict__ cap,
                  const float* __restrict__ b1,
                  const float* __restrict__ b2,
                  float* __restrict__ out) {
    extern __shared__ float sm[];
    float* s_x      = sm;                          // 64*516 = 33024 (x tile, later tanh buffer)
    float* s_w      = s_x + TILE_M * XS;           // 8448 (weight stage, shared by both GEMMs)
    float* s_h1     = s_w + 8448;                  // 64*68 = 4352
    float* s_cap    = s_h1 + TILE_M * HS;          // 512
    float* s_icap   = s_cap + 512;                 // 512
    float* s_eps    = s_icap + 512;                // 64
    float* s_scale  = s_eps + 64;                  // 64
    float* s_rowsum = s_scale + 64;                // 64
    float* s_red    = s_rowsum + 64;               // 17

    const int tid  = threadIdx.x;
    const int row0 = blockIdx.x * TILE_M;

    // ---------------- Phase 0: cap / 1/cap / cap_sum partials / x tile ----------------
    {
        float v = cap[tid];            // NCH == BDIM == 512
        s_cap[tid]  = v;
        s_icap[tid] = 1.0f / v;
        #pragma unroll
        for (int off = 16; off; off >>= 1)
            v += __shfl_down_sync(0xffffffffu, v, off);
        if ((tid & 31) == 0) s_red[tid >> 5] = v;
    }
    const float4* xg = (const float4*)(x_cpm + (size_t)row0 * NCH);
    #pragma unroll
    for (int idx = tid; idx < TILE_M * (NCH / 4); idx += BDIM) {
        int r = idx >> 7, c4 = idx & 127;
        *(float4*)(s_x + r * XS + c4 * 4) = xg[r * (NCH / 4) + c4];
    }
    __syncthreads();

    if (tid == 0) {
        float cs = 0.f;
        #pragma unroll
        for (int i = 0; i < 16; i++) cs += s_red[i];
        s_red[16] = cs;
    }

    // ---------------- Phase 1: raw dot(x_row, cap), 8 threads per row, float4 ----------------
    {
        int r = tid >> 3, s = tid & 7;
        const float4* xr = (const float4*)(s_x + r * XS);
        const float4* cp = (const float4*)s_cap;
        float p = 0.f;
        #pragma unroll
        for (int i = 0; i < 16; i++) {
            int k4 = s + 8 * i;
            float4 a = xr[k4], c = cp[k4];
            p = fmaf(a.x, c.x, p); p = fmaf(a.y, c.y, p);
            p = fmaf(a.z, c.z, p); p = fmaf(a.w, c.w, p);
        }
        p += __shfl_down_sync(0xffffffffu, p, 4, 8);
        p += __shfl_down_sync(0xffffffffu, p, 2, 8);
        p += __shfl_down_sync(0xffffffffu, p, 1, 8);
        if (s == 0) s_eps[r] = p;
    }
    __syncthreads();
    const float cap_sum = s_red[16];
    if (tid < TILE_M)
        s_eps[tid] = x_cons[row0 + tid] - s_eps[tid] / cap_sum;   // epsilon
    // (ordered before GEMM1 epilogue by the chunk-loop barriers)

    // ---------------- Phase 2: GEMM1  h1 = relu([x,eps] @ W1^T + b1) ----------------
    // 2 rows x 4 cols per thread: rg = tid>>4 (rows 2rg,2rg+1), cg = tid&15 (cols 4cg..)
    const int cg = tid & 15;
    const int rg = tid >> 4;
    float acc0[4] = {0.f, 0.f, 0.f, 0.f};
    float acc1[4] = {0.f, 0.f, 0.f, 0.f};

    for (int kc = 0; kc < NCH; kc += 128) {
        __syncthreads();
        const float4* wsrc = (const float4*)(g_w1t + kc * 64);
        #pragma unroll
        for (int i = tid; i < 2048; i += BDIM)
            ((float4*)s_w)[i] = wsrc[i];
        __syncthreads();

        const float* x0p = s_x + (2 * rg) * XS + kc;
        const float* x1p = x0p + XS;
        const float* wp  = s_w + 4 * cg;
        #pragma unroll 4
        for (int kk = 0; kk < 128; kk += 4) {
            float4 a0 = *(const float4*)(x0p + kk);
            float4 a1 = *(const float4*)(x1p + kk);
            float4 w0 = *(const float4*)(wp + (kk + 0) * 64);
            float4 w1 = *(const float4*)(wp + (kk + 1) * 64);
            float4 w2 = *(const float4*)(wp + (kk + 2) * 64);
            float4 w3 = *(const float4*)(wp + (kk + 3) * 64);
            fma4(acc0, a0.x, w0); fma4(acc0, a0.y, w1);
            fma4(acc0, a0.z, w2); fma4(acc0, a0.w, w3);
            fma4(acc1, a1.x, w0); fma4(acc1, a1.y, w1);
            fma4(acc1, a1.z, w2); fma4(acc1, a1.w, w3);
        }
    }
    {
        float4 we = *(const float4*)(g_w1t + 512 * 64 + 4 * cg);  // epsilon column
        float4 bb = *(const float4*)(b1 + 4 * cg);
        float e0 = s_eps[2 * rg], e1 = s_eps[2 * rg + 1];
        float4 h0, h1v;
        h0.x  = fmaxf(acc0[0] + e0 * we.x + bb.x, 0.f);
        h0.y  = fmaxf(acc0[1] + e0 * we.y + bb.y, 0.f);
        h0.z  = fmaxf(acc0[2] + e0 * we.z + bb.z, 0.f);
        h0.w  = fmaxf(acc0[3] + e0 * we.w + bb.w, 0.f);
        h1v.x = fmaxf(acc1[0] + e1 * we.x + bb.x, 0.f);
        h1v.y = fmaxf(acc1[1] + e1 * we.y + bb.y, 0.f);
        h1v.z = fmaxf(acc1[2] + e1 * we.z + bb.z, 0.f);
        h1v.w = fmaxf(acc1[3] + e1 * we.w + bb.w, 0.f);
        *(float4*)(s_h1 + (2 * rg)     * HS + 4 * cg) = h0;
        *(float4*)(s_h1 + (2 * rg + 1) * HS + 4 * cg) = h1v;
    }

    // ---------------- Phase 3: GEMM2 + tanh + row sums (tanh -> s_x) ----------------
    // 4 rows x 4 cols per thread per 128-col chunk: rg2 = tid>>5 (rows 4rg2..), cg2 = tid&31
    const int cg2 = tid & 31;
    const int rg2 = tid >> 5;
    float rsum[4] = {0.f, 0.f, 0.f, 0.f};

    for (int nc = 0; nc < NCH; nc += 128) {
        __syncthreads();
        #pragma unroll
        for (int i = tid; i < 64 * 32; i += BDIM) {
            int kk = i >> 5, c4 = i & 31;
            *(float4*)(s_w + kk * WS2 + 4 * c4) =
                *(const float4*)(g_w2t + kk * 512 + nc + 4 * c4);
        }
        __syncthreads();

        float a2[4][4];
        #pragma unroll
        for (int i = 0; i < 4; i++)
            #pragma unroll
            for (int j = 0; j < 4; j++) a2[i][j] = 0.f;

        const float* hb = s_h1 + (4 * rg2) * HS;
        const float* wp = s_w + 4 * cg2;
        #pragma unroll 4
        for (int kk = 0; kk < HID; kk += 4) {
            float4 h0 = *(const float4*)(hb + 0 * HS + kk);
            float4 h1 = *(const float4*)(hb + 1 * HS + kk);
            float4 h2 = *(const float4*)(hb + 2 * HS + kk);
            float4 h3 = *(const float4*)(hb + 3 * HS + kk);
            float4 w0 = *(const float4*)(wp + (kk + 0) * WS2);
            float4 w1 = *(const float4*)(wp + (kk + 1) * WS2);
            float4 w2 = *(const float4*)(wp + (kk + 2) * WS2);
            float4 w3 = *(const float4*)(wp + (kk + 3) * WS2);
            fma4(a2[0], h0.x, w0); fma4(a2[0], h0.y, w1); fma4(a2[0], h0.z, w2); fma4(a2[0], h0.w, w3);
            fma4(a2[1], h1.x, w0); fma4(a2[1], h1.y, w1); fma4(a2[1], h1.z, w2); fma4(a2[1], h1.w, w3);
            fma4(a2[2], h2.x, w0); fma4(a2[2], h2.y, w1); fma4(a2[2], h2.z, w2); fma4(a2[2], h2.w, w3);
            fma4(a2[3], h3.x, w0); fma4(a2[3], h3.y, w1); fma4(a2[3], h3.z, w2); fma4(a2[3], h3.w, w3);
        }

        float4 bbv = *(const float4*)(b2 + nc + 4 * cg2);
        #pragma unroll
        for (int i = 0; i < 4; i++) {
            float4 t;
            t.x = fast_tanh(a2[i][0] + bbv.x);
            t.y = fast_tanh(a2[i][1] + bbv.y);
            t.z = fast_tanh(a2[i][2] + bbv.z);
            t.w = fast_tanh(a2[i][3] + bbv.w);
            rsum[i] += (t.x + t.y) + (t.z + t.w);
            *(float4*)(s_x + (4 * rg2 + i) * XS + nc + 4 * cg2) = t;
        }
    }

    // row-sum reduce: each warp owns exactly one rg2 (4 rows), full-warp reduction
    #pragma unroll
    for (int i = 0; i < 4; i++) {
        float v = rsum[i];
        #pragma unroll
        for (int off = 16; off; off >>= 1)
            v += __shfl_down_sync(0xffffffffu, v, off);
        if ((tid & 31) == 0) s_rowsum[4 * rg2 + i] = v;
    }
    __syncthreads();
    if (tid < TILE_M)
        s_scale[tid] = s_eps[tid] * cap_sum / s_rowsum[tid];
    __syncthreads();

    // ---------------- Phase 4: out = x + tanh * scale / cap ----------------
    float4* og = (float4*)(out + (size_t)row0 * NCH);
    #pragma unroll
    for (int idx = tid; idx < TILE_M * (NCH / 4); idx += BDIM) {
        int r = idx >> 7, c4 = idx & 127;
        float4 xv = xg[r * (NCH / 4) + c4];
        float4 tv = *(const float4*)(s_x + r * XS + c4 * 4);
        float4 ic = *(const float4*)(s_icap + c4 * 4);
        float  sc = s_scale[r];
        float4 o;
        o.x = fmaf(tv.x * sc, ic.x, xv.x);
        o.y = fmaf(tv.y * sc, ic.y, xv.y);
        o.z = fmaf(tv.z * sc, ic.z, xv.z);
        o.w = fmaf(tv.w * sc, ic.w, xv.w);
        og[r * (NCH / 4) + c4] = o;
    }
}

static constexpr size_t SMEM_BYTES =
    (size_t)(TILE_M * XS + 8448 + TILE_M * HS + 512 + 512 + 64 + 64 + 64 + 17) * sizeof(float);

extern "C" void kernel_launch(void* const* d_in, const int* in_sizes, int n_in,
                              void* d_out, int out_size) {
    const float* x_cpm  = (const float*)d_in[0];
    const float* x_cons = (const float*)d_in[1];
    const float* cap    = (const float*)d_in[2];
    const float* W1     = (const float*)d_in[3];
    const float* b1     = (const float*)d_in[4];
    const float* W2     = (const float*)d_in[5];
    const float* b2     = (const float*)d_in[6];
    float* out = (float*)d_out;

    cudaFuncSetAttribute(fused_kernel, cudaFuncAttributeMaxDynamicSharedMemorySize,
                         (int)SMEM_BYTES);

    prep_kernel<<<129, 256>>>(W1, W2);

    const int B = 65536;
    fused_kernel<<<B / TILE_M, BDIM, SMEM_BYTES>>>(x_cpm, x_cons, cap, b1, b2, out);
}